// round 10
// baseline (speedup 1.0000x reference)
#include <cuda_runtime.h>
#include <cuda_fp16.h>

// QConv2d: 3x3 conv, B=16, C=32, N=64, H=W=56, stride 1, pad 1.
// Exact per-k fp16 (E5M10) requantized accumulation (bit-identical path):
//   p   = fp16(fp32(a * w))  -> FMUL.rn + cvt.rn.f16x2.f32 (packs 2 n-lanes)
//   acc = fp16(acc + p)      -> HADD2
// k order = c*9 + i*3 + j, matching lax.scan order.
//
// R10: wave-quantization fix via fractional depth. Tile = 1 row x 16 n ->
// 3584 tiles; smem 41472B -> exactly 5 CTAs/SM -> conc 740 -> depth 4.843
// -> ceil-eff 96.9% (R8 was 2.018 -> 67%). TB 224, thread = 1 px x 4 n.

#define TB 224

#define ROWP 60                            // padded input row (floats)
#define SIN_FLOATS (32 * 3 * ROWP)         // 5760  -> 23040 B (rows y-1..y+1)
#define SW_FLOATS  (96 * 4 * 12)           // 4608  -> 18432 B packed weights
#define SMEM_BYTES ((SIN_FLOATS + SW_FLOATS) * 4)   // 41472 -> 5 CTAs/SM

__device__ __forceinline__ __half2 cvt_pair(float n0, float n1) {
    unsigned h;
    // cvt.rn.f16x2.f32 d, a, b : a -> upper half, b -> lower half
    asm("cvt.rn.f16x2.f32 %0, %1, %2;" : "=r"(h) : "f"(n1), "f"(n0));
    return *reinterpret_cast<__half2*>(&h);
}

__global__ void __launch_bounds__(TB, 5) qconv2d_kernel(
    const float* __restrict__ x,      // [16][32][56][56]
    const float* __restrict__ w,      // [64][32][3][3] = [64][288]
    const float* __restrict__ bias,   // [64]
    float* __restrict__ out)          // [16][64][56][56]
{
    extern __shared__ float sm[];
    float* sina = sm;                     // [c][r(3)][ROWP]
    float* sw   = sm + SIN_FLOATS;        // [ci(96)][duo(4)][12]: j0 n0..3, j1, j2

    const int y   = blockIdx.x;       // output row 0..55
    const int b   = blockIdx.y;       // batch 0..15
    const int nq  = blockIdx.z;       // n group 0..3 -> n = 16*nq .. 16*nq+15
    const int tid = threadIdx.x;

    // ---- weights: quantize to fp16 value, pack [(ci)][duo][j*4 + l] ----
    for (int idx = tid; idx < 16 * 288; idx += TB) {
        int nc = idx / 288;
        int k  = idx % 288;           // coalesced over k
        int ci = k / 3;               // c*3 + i
        int j  = k % 3;
        int duo = nc >> 2;            // 4 n per duo
        int l   = nc & 3;
        sw[(ci * 4 + duo) * 12 + j * 4 + l] =
            __half2float(__float2half_rn(w[(nq * 16 + nc) * 288 + k]));
    }

    // ---- input rows y-1..y+1, 32 ch, padded rows of 60 (x offset by 1) ----
    const float* xb = x + (size_t)b * 32 * 56 * 56;
    for (int idx = tid; idx < SIN_FLOATS; idx += TB) {
        int c  = idx / (3 * ROWP);
        int rr = idx % (3 * ROWP);
        int r  = rr / ROWP;
        int xs = rr % ROWP;
        int yg = y - 1 + r;
        int xg = xs - 1;
        float v = 0.0f;
        if (yg >= 0 && yg < 56 && xg >= 0 && xg < 56)
            v = xb[(c * 56 + yg) * 56 + xg];
        sina[idx] = v;
    }
    __syncthreads();

    const int lane = tid & 31;
    const int wrp  = tid >> 5;            // 0..6
    const int duo  = lane & 3;            // n duo: n = nq*16 + 4*duo .. +3
    const int px   = wrp * 8 + (lane >> 2);   // output x 0..55

    __half2 c01 = __float2half2_rn(0.0f);     // (n0, n1)
    __half2 c23 = c01;                        // (n2, n3)

    const float* ap = sina + px;          // smem idx px,px+1,px+2 = x-1,x,x+1
    const float* wp = sw + duo * 12;

    #pragma unroll 2
    for (int c = 0; c < 32; ++c) {
        #pragma unroll
        for (int i = 0; i < 3; ++i) {
            const float* ar = ap + (c * 3 + i) * ROWP;
            float aL = ar[0], aC = ar[1], aR = ar[2];

            const float* wr = wp + (c * 3 + i) * 48;    // 4 duos x 12 floats
            float4 W0 = *reinterpret_cast<const float4*>(wr);      // j=0: n0..n3
            float4 W1 = *reinterpret_cast<const float4*>(wr + 4);  // j=1
            float4 W2 = *reinterpret_cast<const float4*>(wr + 8);  // j=2

            // j = 0 (input x-1), j = 1 (x), j = 2 (x+1) -- sequential in k
            c01 = __hadd2(c01, cvt_pair(aL * W0.x, aL * W0.y));
            c23 = __hadd2(c23, cvt_pair(aL * W0.z, aL * W0.w));
            c01 = __hadd2(c01, cvt_pair(aC * W1.x, aC * W1.y));
            c23 = __hadd2(c23, cvt_pair(aC * W1.z, aC * W1.w));
            c01 = __hadd2(c01, cvt_pair(aR * W2.x, aR * W2.y));
            c23 = __hadd2(c23, cvt_pair(aR * W2.z, aR * W2.w));
        }
    }

    // ---- epilogue: out = fp32(fp16(acc + fp16(bias))) ----
    const int n0 = nq * 16 + 4 * duo;
    __half2 qb01 = __halves2half2(__float2half_rn(bias[n0]),
                                  __float2half_rn(bias[n0 + 1]));
    __half2 qb23 = __halves2half2(__float2half_rn(bias[n0 + 2]),
                                  __float2half_rn(bias[n0 + 3]));

    __half2 r01 = __hadd2(c01, qb01);
    __half2 r23 = __hadd2(c23, qb23);

    size_t ob = (((size_t)b * 64 + n0) * 56 + y) * 56 + px;
    out[ob]               = __low2float(r01);
    out[ob + 3136]        = __high2float(r01);   // 3136 = 56*56
    out[ob + 2 * 3136]    = __low2float(r23);
    out[ob + 3 * 3136]    = __high2float(r23);
}

extern "C" void kernel_launch(void* const* d_in, const int* in_sizes, int n_in,
                              void* d_out, int out_size)
{
    const float* x    = (const float*)d_in[0];
    const float* w    = (const float*)d_in[1];
    const float* bias = (const float*)d_in[2];
    float* out = (float*)d_out;

    cudaFuncSetAttribute(qconv2d_kernel,
                         cudaFuncAttributeMaxDynamicSharedMemorySize,
                         SMEM_BYTES);

    dim3 grid(56, 16, 4);   // (row, batch, n group of 16)
    qconv2d_kernel<<<grid, TB, SMEM_BYTES>>>(x, w, bias, out);
}

// round 11
// speedup vs baseline: 1.5436x; 1.5436x over previous
#include <cuda_runtime.h>
#include <cuda_fp16.h>

// QConv2d: 3x3 conv, B=16, C=32, N=64, H=W=56, stride 1, pad 1.
// Exact per-k fp16 (E5M10) requantized accumulation (bit-identical path):
//   p   = fp16(fp32(a * w))  -> FMUL.rn + cvt.rn.f16x2.f32 (packs 2 n-lanes)
//   acc = fp16(acc + p)      -> HADD2
// k order = c*9 + i*3 + j, matching lax.scan order.
//
// R11 = R8 (best: 8px/thread, 8 chains, low wavefronts) + fp16-packed weights
// (exact H2F re-expansion) to shrink smem 64512 -> 55296 B => 4 CTAs/SM,
// 28 warps, conc 592 (depth 1.51 with a fast second wave) vs R8's 444/2.02.

#define TB 224

#define ROWP 60                            // padded input row (floats)
#define NROWS 6                            // 4 output rows + halo
#define SIN_FLOATS (32 * NROWS * ROWP)     // 11520 -> 46080 B
#define SW_HALVES  (96 * 8 * 8)            // [(ci)][np(8)][8 halves] -> 9216 B
#define SMEM_BYTES (SIN_FLOATS * 4 + SW_HALVES * 2)   // 55296 -> 4 CTAs/SM

__device__ __forceinline__ __half2 cvt_pair(float n0, float n1) {
    unsigned h;
    // cvt.rn.f16x2.f32 d, a, b : a -> upper half, b -> lower half
    asm("cvt.rn.f16x2.f32 %0, %1, %2;" : "=r"(h) : "f"(n1), "f"(n0));
    return *reinterpret_cast<__half2*>(&h);
}

__global__ void __launch_bounds__(TB, 4) qconv2d_kernel(
    const float* __restrict__ x,      // [16][32][56][56]
    const float* __restrict__ w,      // [64][32][3][3] = [64][288]
    const float* __restrict__ bias,   // [64]
    float* __restrict__ out)          // [16][64][56][56]
{
    extern __shared__ float sm[];
    float*  sin = sm;                                  // [c][r(6)][ROWP]
    __half* swh = reinterpret_cast<__half*>(sm + SIN_FLOATS);  // packed weights

    const int yq  = blockIdx.x;       // row quad 0..13 -> rows 4*yq .. 4*yq+3
    const int b   = blockIdx.y;       // batch 0..15
    const int nq  = blockIdx.z;       // n quarter 0..3 -> n = 16*nq ..
    const int tid = threadIdx.x;
    const int y0  = 4 * yq;

    // ---- weights: quantize to fp16, pack [ci][np][j*2+l] (16B records) ----
    for (int idx = tid; idx < 16 * 288; idx += TB) {
        int nc = idx / 288;
        int k  = idx % 288;           // coalesced over k
        int ci = k / 3;               // c*3 + i
        int j  = k % 3;
        int np = nc >> 1;
        int l  = nc & 1;
        swh[(ci * 8 + np) * 8 + j * 2 + l] =
            __float2half_rn(w[(nq * 16 + nc) * 288 + k]);
    }

    // ---- input rows y0-1..y0+4, 32 ch, padded rows of 60 (x offset by 1) ----
    const float* xb = x + (size_t)b * 32 * 56 * 56;
    for (int idx = tid; idx < SIN_FLOATS; idx += TB) {
        int c   = idx / (NROWS * ROWP);
        int rr  = idx % (NROWS * ROWP);
        int r   = rr / ROWP;
        int xs  = rr % ROWP;
        int yg  = y0 - 1 + r;
        int xg  = xs - 1;
        float v = 0.0f;
        if (yg >= 0 && yg < 56 && xg >= 0 && xg < 56)
            v = xb[(c * 56 + yg) * 56 + xg];
        sin[idx] = v;
    }
    __syncthreads();

    const int lane = tid & 31;
    const int wrp  = tid >> 5;            // 0..6
    const int np   = lane & 7;            // n-pair within quarter (0..7)
    const int h    = lane >> 3;           // px group slot 0..3
    const int grp  = wrp * 4 + h;         // 0..27
    const int row  = grp / 7;             // 0..3 (output row within quad)
    const int x0   = (grp % 7) * 8;       // output x base, 8 px per thread

    __half2 acc[8];
    #pragma unroll
    for (int p = 0; p < 8; ++p) acc[p] = __float2half2_rn(0.0f);

    const __half* swt = swh + np * 8;     // +ci*64 halves per (c,i)
    const float*  ab  = sin + row * ROWP + x0;   // 16B aligned

    #pragma unroll 2
    for (int c = 0; c < 32; ++c) {
        #pragma unroll
        for (int i = 0; i < 3; ++i) {
            const float* ar = ab + (c * NROWS + i) * ROWP;
            float4 a03 = *reinterpret_cast<const float4*>(ar);
            float4 a47 = *reinterpret_cast<const float4*>(ar + 4);
            float2 a89 = *reinterpret_cast<const float2*>(ar + 8);
            float av[10] = { a03.x, a03.y, a03.z, a03.w,
                             a47.x, a47.y, a47.z, a47.w,
                             a89.x, a89.y };

            // one LDS.128 (128B warp span = 1 wavefront): three j-pairs fp16
            uint4 wb = *reinterpret_cast<const uint4*>(swt + (c * 3 + i) * 64);
            float2 w0 = __half22float2(*reinterpret_cast<__half2*>(&wb.x)); // j=0
            float2 w1 = __half22float2(*reinterpret_cast<__half2*>(&wb.y)); // j=1
            float2 w2 = __half22float2(*reinterpret_cast<__half2*>(&wb.z)); // j=2

            #pragma unroll
            for (int p = 0; p < 8; ++p)
                acc[p] = __hadd2(acc[p], cvt_pair(av[p] * w0.x, av[p] * w0.y));
            #pragma unroll
            for (int p = 0; p < 8; ++p)
                acc[p] = __hadd2(acc[p], cvt_pair(av[p + 1] * w1.x, av[p + 1] * w1.y));
            #pragma unroll
            for (int p = 0; p < 8; ++p)
                acc[p] = __hadd2(acc[p], cvt_pair(av[p + 2] * w2.x, av[p + 2] * w2.y));
        }
    }

    // ---- epilogue: out = fp32(fp16(acc + fp16(bias))) ----
    const int n0 = nq * 16 + 2 * np;
    __half2 qb = __halves2half2(__float2half_rn(bias[n0]),
                                __float2half_rn(bias[n0 + 1]));

    float o0v[8], o1v[8];
    #pragma unroll
    for (int p = 0; p < 8; ++p) {
        __half2 r = __hadd2(acc[p], qb);
        o0v[p] = __low2float(r);
        o1v[p] = __high2float(r);
    }

    const int y = y0 + row;
    size_t o0 = (((size_t)b * 64 + n0) * 56 + y) * 56 + x0;
    size_t o1 = (((size_t)b * 64 + n0 + 1) * 56 + y) * 56 + x0;
    #pragma unroll
    for (int q = 0; q < 2; ++q) {
        float4 v0 = make_float4(o0v[q*4+0], o0v[q*4+1], o0v[q*4+2], o0v[q*4+3]);
        float4 v1 = make_float4(o1v[q*4+0], o1v[q*4+1], o1v[q*4+2], o1v[q*4+3]);
        *reinterpret_cast<float4*>(out + o0 + q * 4) = v0;
        *reinterpret_cast<float4*>(out + o1 + q * 4) = v1;
    }
}

extern "C" void kernel_launch(void* const* d_in, const int* in_sizes, int n_in,
                              void* d_out, int out_size)
{
    const float* x    = (const float*)d_in[0];
    const float* w    = (const float*)d_in[1];
    const float* bias = (const float*)d_in[2];
    float* out = (float*)d_out;

    cudaFuncSetAttribute(qconv2d_kernel,
                         cudaFuncAttributeMaxDynamicSharedMemorySize,
                         SMEM_BYTES);

    dim3 grid(14, 16, 4);   // (row quad, batch, n quarter)
    qconv2d_kernel<<<grid, TB, SMEM_BYTES>>>(x, w, bias, out);
}